// round 8
// baseline (speedup 1.0000x reference)
#include <cuda_runtime.h>

// NormalShader fused, R8: single kernel. First PACKB blocks build the packed
// per-face normal table, all blocks sync via a global atomic barrier
// (deadlock-free: PACKB < wave-1 residency; late blocks see it done), then
// R5's pixel body runs. Counters self-reset for graph-replay determinism.

#define K_SAMP 8
#define BLK 256
#define PPT 2
#define F_MAX 200000
#define PACKB 512

__device__ float4 g_packed[F_MAX * 3];   // 9.6 MB, L2-resident
__device__ unsigned int g_done = 0;
__device__ unsigned int g_exit = 0;

__global__ __launch_bounds__(BLK, 5)
void normal_shader_kernel(const int*   __restrict__ p2f,
                          const float* __restrict__ bary,
                          const float* __restrict__ zbuf,
                          const float* __restrict__ dists,
                          const float* __restrict__ vnorm,
                          const int*   __restrict__ faces,
                          float*       __restrict__ out,
                          int npix, int ftotal3)
{
    __shared__ float s[BLK * PPT * 3];

    const float ZFAR = 100.0f;
    const float INV_ZRANGE = 1.0f / 99.0f;
    const float INV_SIGMA = 1.0e4f;
    const float INV_GAMMA = 1.0e4f;
    const float EPS = 1.0e-10f;
    const float BGDIR = 0.577350269f;

    int tid = threadIdx.x;
    int packb = (gridDim.x < PACKB) ? gridDim.x : PACKB;

    // ================= pack phase (first packb blocks) =================
    if (blockIdx.x < (unsigned)packb) {
        for (int j = blockIdx.x * BLK + tid; j < ftotal3; j += packb * BLK) {
            int v = faces[j];
            const float* n = vnorm + v * 3;
            g_packed[j] = make_float4(n[0], n[1], n[2], 0.0f);
        }
        __threadfence();
        __syncthreads();
        if (tid == 0) atomicAdd(&g_done, 1u);
    }

    // ================= global barrier =================
    if (tid == 0) {
        unsigned int d;
        do { d = atomicOr(&g_done, 0u); } while (d < (unsigned)packb);
        __threadfence();
    }
    __syncthreads();

    // ================= pixel body (R5) =================
    int base = blockIdx.x * (BLK * PPT);

    #pragma unroll
    for (int p = 0; p < PPT; p++) {
        int pix  = base + p * BLK + tid;
        int pixc = (pix < npix) ? pix : 0;

        int4   f0 = reinterpret_cast<const int4*  >(p2f )[pixc * 2 + 0];
        int4   f1 = reinterpret_cast<const int4*  >(p2f )[pixc * 2 + 1];
        float4 z0 = reinterpret_cast<const float4*>(zbuf)[pixc * 2 + 0];
        float4 z1 = reinterpret_cast<const float4*>(zbuf)[pixc * 2 + 1];

        int   pf[K_SAMP] = {f0.x, f0.y, f0.z, f0.w, f1.x, f1.y, f1.z, f1.w};
        float zv[K_SAMP] = {z0.x, z0.y, z0.z, z0.w, z1.x, z1.y, z1.z, z1.w};

        float zinv[K_SAMP];
        float zmax = 0.0f;
        int   ksel = -1;
        int   fsel = 0;
        #pragma unroll
        for (int k = 0; k < K_SAMP; k++) {
            float zi = (pf[k] >= 0) ? (ZFAR - zv[k]) * INV_ZRANGE : 0.0f;
            zinv[k] = zi;
            if (zi > zmax) { zmax = zi; ksel = k; fsel = pf[k]; }
        }
        bool valid = (ksel >= 0);

        int f  = valid ? fsel : 0;
        float4 q0 = g_packed[f * 3 + 0];
        float4 q1 = g_packed[f * 3 + 1];
        float4 q2 = g_packed[f * 3 + 2];

        int bb = (pixc * K_SAMP + (valid ? ksel : 0)) * 3;
        float b0 = bary[bb + 0];
        float b1 = bary[bb + 1];
        float b2 = bary[bb + 2];

        float nx = fmaf(b0, q0.x, fmaf(b1, q1.x, b2 * q2.x));
        float ny = fmaf(b0, q0.y, fmaf(b1, q1.y, b2 * q2.y));
        float nz = fmaf(b0, q0.z, fmaf(b1, q1.z, b2 * q2.z));

        float thresh = zmax - 1.5e-3f;
        bool ties = false;
        #pragma unroll
        for (int k = 0; k < K_SAMP; k++)
            ties |= (k != ksel && pf[k] >= 0 && zinv[k] > thresh);

        float vx, vy, vz;
        if (!valid) {
            vx = BGDIR; vy = BGDIR; vz = BGDIR;
        } else if (!ties && zmax >= 2.4e-3f) {
            vx = nx; vy = ny; vz = nz;
        } else {
            float zm = fmaxf(zmax, EPS);
            float delta = EPS;
            if (zmax < 2.4e-3f)
                delta = fmaxf(__expf((EPS - zm) * INV_GAMMA), EPS);

            float4 d0 = reinterpret_cast<const float4*>(dists)[pixc * 2 + 0];
            float4 d1 = reinterpret_cast<const float4*>(dists)[pixc * 2 + 1];
            float dv[K_SAMP] = {d0.x, d0.y, d0.z, d0.w, d1.x, d1.y, d1.z, d1.w};

            float ax = 0.0f, ay = 0.0f, az = 0.0f;
            float lim = zm - 3.0e-3f;
            #pragma unroll
            for (int k = 0; k < K_SAMP; k++) {
                if (pf[k] < 0 || zinv[k] <= lim) continue;
                float ew = __expf((zinv[k] - zm) * INV_GAMMA);
                float prob = 1.0f / (1.0f + __expf(dv[k] * INV_SIGMA));
                float w = prob * ew;

                int ff = pf[k];
                float4 m0 = g_packed[ff * 3 + 0];
                float4 m1 = g_packed[ff * 3 + 1];
                float4 m2 = g_packed[ff * 3 + 2];

                int bk = (pixc * K_SAMP + k) * 3;
                float c0 = bary[bk + 0];
                float c1 = bary[bk + 1];
                float c2 = bary[bk + 2];

                float gx = fmaf(c0, m0.x, fmaf(c1, m1.x, c2 * m2.x));
                float gy = fmaf(c0, m0.y, fmaf(c1, m1.y, c2 * m2.y));
                float gz = fmaf(c0, m0.z, fmaf(c1, m1.z, c2 * m2.z));

                ax = fmaf(w, gx, ax);
                ay = fmaf(w, gy, ay);
                az = fmaf(w, gz, az);
            }
            vx = ax + delta;
            vy = ay + delta;
            vz = az + delta;
        }

        float nn  = fmaf(vx, vx, fmaf(vy, vy, vz * vz));
        float inv = rsqrtf(fmaxf(nn, 1e-24f));
        int si = (p * BLK + tid) * 3;
        s[si + 0] = fmaf(vx * inv, 0.5f, 0.5f);
        s[si + 1] = fmaf(vy * inv, 0.5f, 0.5f);
        s[si + 2] = fmaf(vz * inv, 0.5f, 0.5f);
    }

    __syncthreads();

    // ---- coalesced float4 stores ----
    const int NF  = BLK * PPT * 3;       // 1536 floats
    const int NV4 = NF / 4;              // 384
    long fbase   = (long)blockIdx.x * NF;
    long fltotal = (long)npix * 3;
    if (fbase + NF <= fltotal) {
        #pragma unroll
        for (int i = tid; i < NV4; i += BLK) {
            reinterpret_cast<float4*>(out)[fbase / 4 + i] =
                reinterpret_cast<const float4*>(s)[i];
        }
    } else {
        for (int i = tid; i < NF; i += BLK) {
            long fi = fbase + i;
            if (fi < fltotal) out[fi] = s[i];
        }
    }

    // ================= counter self-reset for graph replays =================
    __syncthreads();
    if (tid == 0) {
        unsigned int t = atomicAdd(&g_exit, 1u);
        if (t == gridDim.x - 1) {
            g_done = 0;
            g_exit = 0;
            __threadfence();
        }
    }
}

extern "C" void kernel_launch(void* const* d_in, const int* in_sizes, int n_in,
                              void* d_out, int out_size)
{
    const int*   p2f   = (const int*  )d_in[0];
    const float* bary  = (const float*)d_in[1];
    const float* zbuf  = (const float*)d_in[2];
    const float* dists = (const float*)d_in[3];
    const float* vnorm = (const float*)d_in[4];
    const int*   faces = (const int*  )d_in[5];
    float* out = (float*)d_out;

    int ftotal3 = in_sizes[5];                 // F*3
    if (ftotal3 > F_MAX * 3) ftotal3 = F_MAX * 3;
    int npix = in_sizes[0] / K_SAMP;

    int blocks = (npix + BLK * PPT - 1) / (BLK * PPT);
    normal_shader_kernel<<<blocks, BLK>>>(p2f, bary, zbuf, dists,
                                          vnorm, faces, out, npix, ftotal3);
}

// round 9
// speedup vs baseline: 1.1565x; 1.1565x over previous
#include <cuda_runtime.h>

// NormalShader fused, R9: R5 two-kernel structure; main kernel front-batches
// both pixels' row loads as scalars (overlapped DRAM latency), tie threshold
// tightened to 1e-3.

#define K_SAMP 8
#define BLK 256
#define PPT 2
#define F_MAX 200000

__device__ float4 g_packed[F_MAX * 3];   // 9.6 MB, L2-resident

__global__ __launch_bounds__(256)
void pack_faces_kernel(const int*   __restrict__ faces,
                       const float* __restrict__ vnorm,
                       int total)                  // total = F*3
{
    int j = blockIdx.x * blockDim.x + threadIdx.x;
    if (j >= total) return;
    int v = faces[j];
    const float* n = vnorm + v * 3;
    g_packed[j] = make_float4(n[0], n[1], n[2], 0.0f);
}

__global__ __launch_bounds__(BLK, 4)
void normal_shader_kernel(const int*   __restrict__ p2f,
                          const float* __restrict__ bary,
                          const float* __restrict__ zbuf,
                          const float* __restrict__ dists,
                          float*       __restrict__ out,
                          int npix)
{
    __shared__ float s[BLK * PPT * 3];

    const float ZFAR = 100.0f;
    const float INV_ZRANGE = 1.0f / 99.0f;
    const float INV_SIGMA = 1.0e4f;
    const float INV_GAMMA = 1.0e4f;
    const float EPS = 1.0e-10f;
    const float BGDIR = 0.577350269f;

    int tid  = threadIdx.x;
    int base = blockIdx.x * (BLK * PPT);

    int pixA = base + tid;
    int pixB = base + BLK + tid;
    int pA = (pixA < npix) ? pixA : 0;
    int pB = (pixB < npix) ? pixB : 0;

    // ======== front-batched row loads: both pixels' chains in flight ========
    int4   fa0 = reinterpret_cast<const int4*  >(p2f )[pA * 2 + 0];
    int4   fa1 = reinterpret_cast<const int4*  >(p2f )[pA * 2 + 1];
    int4   fb0 = reinterpret_cast<const int4*  >(p2f )[pB * 2 + 0];
    int4   fb1 = reinterpret_cast<const int4*  >(p2f )[pB * 2 + 1];
    float4 za0 = reinterpret_cast<const float4*>(zbuf)[pA * 2 + 0];
    float4 za1 = reinterpret_cast<const float4*>(zbuf)[pA * 2 + 1];
    float4 zb0 = reinterpret_cast<const float4*>(zbuf)[pB * 2 + 0];
    float4 zb1 = reinterpret_cast<const float4*>(zbuf)[pB * 2 + 1];

    #pragma unroll
    for (int p = 0; p < PPT; p++) {
        int pixc = (p == 0) ? pA : pB;
        int4   f0 = (p == 0) ? fa0 : fb0;
        int4   f1 = (p == 0) ? fa1 : fb1;
        float4 z0 = (p == 0) ? za0 : zb0;
        float4 z1 = (p == 0) ? za1 : zb1;

        int   pf[K_SAMP] = {f0.x, f0.y, f0.z, f0.w, f1.x, f1.y, f1.z, f1.w};
        float zv[K_SAMP] = {z0.x, z0.y, z0.z, z0.w, z1.x, z1.y, z1.z, z1.w};

        // ---- z_inv + argmax (track face id: no dynamic reg indexing) ----
        float zinv[K_SAMP];
        float zmax = 0.0f;
        int   ksel = -1;
        int   fsel = 0;
        #pragma unroll
        for (int k = 0; k < K_SAMP; k++) {
            float zi = (pf[k] >= 0) ? (ZFAR - zv[k]) * INV_ZRANGE : 0.0f;
            zinv[k] = zi;
            if (zi > zmax) { zmax = zi; ksel = k; fsel = pf[k]; }
        }
        bool valid = (ksel >= 0);

        // ---- unconditional gather for argmax sample: 3 x LDG.128 ----
        int f  = valid ? fsel : 0;
        float4 q0 = g_packed[f * 3 + 0];
        float4 q1 = g_packed[f * 3 + 1];
        float4 q2 = g_packed[f * 3 + 2];

        int bb = (pixc * K_SAMP + (valid ? ksel : 0)) * 3;
        float b0 = bary[bb + 0];
        float b1 = bary[bb + 1];
        float b2 = bary[bb + 2];

        float nx = fmaf(b0, q0.x, fmaf(b1, q1.x, b2 * q2.x));
        float ny = fmaf(b0, q0.y, fmaf(b1, q1.y, b2 * q2.y));
        float nz = fmaf(b0, q0.z, fmaf(b1, q1.z, b2 * q2.z));

        // ---- near-tie detection (e^-10 ~ 4.5e-5 << 1e-3 tol) ----
        float thresh = zmax - 1.0e-3f;
        bool ties = false;
        #pragma unroll
        for (int k = 0; k < K_SAMP; k++)
            ties |= (k != ksel && pf[k] >= 0 && zinv[k] > thresh);

        float vx, vy, vz;
        if (!valid) {
            vx = BGDIR; vy = BGDIR; vz = BGDIR;      // all background
        } else if (!ties && zmax >= 2.4e-3f) {
            // FAST: single contributor; prob & denom cancel in normalize
            vx = nx; vy = ny; vz = nz;
        } else {
            // SLOW (rare): full weights for samples within 3e-3 of max
            float zm = fmaxf(zmax, EPS);
            float delta = EPS;
            if (zmax < 2.4e-3f)
                delta = fmaxf(__expf((EPS - zm) * INV_GAMMA), EPS);

            float4 d0 = reinterpret_cast<const float4*>(dists)[pixc * 2 + 0];
            float4 d1 = reinterpret_cast<const float4*>(dists)[pixc * 2 + 1];
            float dv[K_SAMP] = {d0.x, d0.y, d0.z, d0.w, d1.x, d1.y, d1.z, d1.w};

            float ax = 0.0f, ay = 0.0f, az = 0.0f;
            float lim = zm - 3.0e-3f;
            #pragma unroll
            for (int k = 0; k < K_SAMP; k++) {
                if (pf[k] < 0 || zinv[k] <= lim) continue;
                float ew = __expf((zinv[k] - zm) * INV_GAMMA);
                float prob = 1.0f / (1.0f + __expf(dv[k] * INV_SIGMA));
                float w = prob * ew;

                int ff = pf[k];
                float4 m0 = g_packed[ff * 3 + 0];
                float4 m1 = g_packed[ff * 3 + 1];
                float4 m2 = g_packed[ff * 3 + 2];

                int bk = (pixc * K_SAMP + k) * 3;
                float c0 = bary[bk + 0];
                float c1 = bary[bk + 1];
                float c2 = bary[bk + 2];

                float gx = fmaf(c0, m0.x, fmaf(c1, m1.x, c2 * m2.x));
                float gy = fmaf(c0, m0.y, fmaf(c1, m1.y, c2 * m2.y));
                float gz = fmaf(c0, m0.z, fmaf(c1, m1.z, c2 * m2.z));

                ax = fmaf(w, gx, ax);
                ay = fmaf(w, gy, ay);
                az = fmaf(w, gz, az);
            }
            vx = ax + delta;
            vy = ay + delta;
            vz = az + delta;
        }

        // ---- normalize + map to [0,1], stage in smem ----
        float nn  = fmaf(vx, vx, fmaf(vy, vy, vz * vz));
        float inv = rsqrtf(fmaxf(nn, 1e-24f));
        int si = (p * BLK + tid) * 3;
        s[si + 0] = fmaf(vx * inv, 0.5f, 0.5f);
        s[si + 1] = fmaf(vy * inv, 0.5f, 0.5f);
        s[si + 2] = fmaf(vz * inv, 0.5f, 0.5f);
    }

    __syncthreads();

    // ---- coalesced float4 stores ----
    const int NF  = BLK * PPT * 3;       // 1536 floats
    const int NV4 = NF / 4;              // 384
    long fbase  = (long)blockIdx.x * NF;
    long ftotal = (long)npix * 3;
    if (fbase + NF <= ftotal) {
        #pragma unroll
        for (int i = tid; i < NV4; i += BLK) {
            reinterpret_cast<float4*>(out)[fbase / 4 + i] =
                reinterpret_cast<const float4*>(s)[i];
        }
    } else {
        for (int i = tid; i < NF; i += BLK) {
            long fi = fbase + i;
            if (fi < ftotal) out[fi] = s[i];
        }
    }
}

extern "C" void kernel_launch(void* const* d_in, const int* in_sizes, int n_in,
                              void* d_out, int out_size)
{
    const int*   p2f   = (const int*  )d_in[0];
    const float* bary  = (const float*)d_in[1];
    const float* zbuf  = (const float*)d_in[2];
    const float* dists = (const float*)d_in[3];
    const float* vnorm = (const float*)d_in[4];
    const int*   faces = (const int*  )d_in[5];
    float* out = (float*)d_out;

    int total = in_sizes[5];                 // F*3
    if (total > F_MAX * 3) total = F_MAX * 3;
    int npix = in_sizes[0] / K_SAMP;

    pack_faces_kernel<<<(total + 255) / 256, 256>>>(faces, vnorm, total);

    int blocks = (npix + BLK * PPT - 1) / (BLK * PPT);
    normal_shader_kernel<<<blocks, BLK>>>(p2f, bary, zbuf, dists, out, npix);
}

// round 10
// speedup vs baseline: 1.2910x; 1.1162x over previous
#include <cuda_runtime.h>
#include <cuda_fp16.h>

// NormalShader fused, R10: R5 structure + fp16-packed 32B face-normal table
// (one cache line per gather instead of 1-2 lines x 3 loads).

#define K_SAMP 8
#define BLK 256
#define PPT 2
#define F_MAX 200000

struct __align__(32) PackedFace {
    uint4 a;   // h0..h7 = n0x n0y n0z n1x n1y n1z n2x n2y
    uint4 b;   // b.x low half = n2z; rest pad
};

__device__ PackedFace g_packed[F_MAX];   // 6.4 MB, L2-resident

__global__ __launch_bounds__(256)
void pack_faces_kernel(const int*   __restrict__ faces,
                       const float* __restrict__ vnorm,
                       int F)
{
    int f = blockIdx.x * blockDim.x + threadIdx.x;
    if (f >= F) return;
    int v0 = faces[f * 3 + 0];
    int v1 = faces[f * 3 + 1];
    int v2 = faces[f * 3 + 2];
    const float* n0 = vnorm + v0 * 3;
    const float* n1 = vnorm + v1 * 3;
    const float* n2 = vnorm + v2 * 3;

    __half2 h01 = __floats2half2_rn(n0[0], n0[1]);
    __half2 h23 = __floats2half2_rn(n0[2], n1[0]);
    __half2 h45 = __floats2half2_rn(n1[1], n1[2]);
    __half2 h67 = __floats2half2_rn(n2[0], n2[1]);
    __half2 h8p = __floats2half2_rn(n2[2], 0.0f);

    PackedFace pf;
    pf.a = make_uint4(*(unsigned*)&h01, *(unsigned*)&h23,
                      *(unsigned*)&h45, *(unsigned*)&h67);
    pf.b = make_uint4(*(unsigned*)&h8p, 0u, 0u, 0u);
    g_packed[f] = pf;
}

// decode entry -> blended normal
__device__ __forceinline__ void blend_normal(uint4 A, unsigned B,
                                             float b0, float b1, float b2,
                                             float& nx, float& ny, float& nz)
{
    float2 p0 = __half22float2(*(__half2*)&A.x);  // n0x n0y
    float2 p1 = __half22float2(*(__half2*)&A.y);  // n0z n1x
    float2 p2 = __half22float2(*(__half2*)&A.z);  // n1y n1z
    float2 p3 = __half22float2(*(__half2*)&A.w);  // n2x n2y
    float2 p4 = __half22float2(*(__half2*)&B);    // n2z --
    nx = fmaf(b0, p0.x, fmaf(b1, p1.y, b2 * p3.x));
    ny = fmaf(b0, p0.y, fmaf(b1, p2.x, b2 * p3.y));
    nz = fmaf(b0, p1.x, fmaf(b1, p2.y, b2 * p4.x));
}

__global__ __launch_bounds__(BLK, 5)
void normal_shader_kernel(const int*   __restrict__ p2f,
                          const float* __restrict__ bary,
                          const float* __restrict__ zbuf,
                          const float* __restrict__ dists,
                          float*       __restrict__ out,
                          int npix)
{
    __shared__ float s[BLK * PPT * 3];

    const float ZFAR = 100.0f;
    const float INV_ZRANGE = 1.0f / 99.0f;
    const float INV_SIGMA = 1.0e4f;
    const float INV_GAMMA = 1.0e4f;
    const float EPS = 1.0e-10f;
    const float BGDIR = 0.577350269f;

    int tid  = threadIdx.x;
    int base = blockIdx.x * (BLK * PPT);

    #pragma unroll
    for (int p = 0; p < PPT; p++) {
        int pix  = base + p * BLK + tid;
        int pixc = (pix < npix) ? pix : 0;

        int4   f0 = reinterpret_cast<const int4*  >(p2f )[pixc * 2 + 0];
        int4   f1 = reinterpret_cast<const int4*  >(p2f )[pixc * 2 + 1];
        float4 z0 = reinterpret_cast<const float4*>(zbuf)[pixc * 2 + 0];
        float4 z1 = reinterpret_cast<const float4*>(zbuf)[pixc * 2 + 1];

        int   pf[K_SAMP] = {f0.x, f0.y, f0.z, f0.w, f1.x, f1.y, f1.z, f1.w};
        float zv[K_SAMP] = {z0.x, z0.y, z0.z, z0.w, z1.x, z1.y, z1.z, z1.w};

        float zinv[K_SAMP];
        float zmax = 0.0f;
        int   ksel = -1;
        int   fsel = 0;
        #pragma unroll
        for (int k = 0; k < K_SAMP; k++) {
            float zi = (pf[k] >= 0) ? (ZFAR - zv[k]) * INV_ZRANGE : 0.0f;
            zinv[k] = zi;
            if (zi > zmax) { zmax = zi; ksel = k; fsel = pf[k]; }
        }
        bool valid = (ksel >= 0);

        // ---- unconditional gather: one 32B entry (single cache line) ----
        int f = valid ? fsel : 0;
        uint4    A = g_packed[f].a;
        unsigned B = g_packed[f].b.x;

        int bb = (pixc * K_SAMP + (valid ? ksel : 0)) * 3;
        float b0 = bary[bb + 0];
        float b1 = bary[bb + 1];
        float b2 = bary[bb + 2];

        float nx, ny, nz;
        blend_normal(A, B, b0, b1, b2, nx, ny, nz);

        // ---- near-tie detection (e^-10 ~ 4.5e-5 << tol) ----
        float thresh = zmax - 1.0e-3f;
        bool ties = false;
        #pragma unroll
        for (int k = 0; k < K_SAMP; k++)
            ties |= (k != ksel && pf[k] >= 0 && zinv[k] > thresh);

        float vx, vy, vz;
        if (!valid) {
            vx = BGDIR; vy = BGDIR; vz = BGDIR;
        } else if (!ties && zmax >= 2.4e-3f) {
            vx = nx; vy = ny; vz = nz;
        } else {
            // SLOW (rare): full softmax blend
            float zm = fmaxf(zmax, EPS);
            float delta = EPS;
            if (zmax < 2.4e-3f)
                delta = fmaxf(__expf((EPS - zm) * INV_GAMMA), EPS);

            float4 d0 = reinterpret_cast<const float4*>(dists)[pixc * 2 + 0];
            float4 d1 = reinterpret_cast<const float4*>(dists)[pixc * 2 + 1];
            float dv[K_SAMP] = {d0.x, d0.y, d0.z, d0.w, d1.x, d1.y, d1.z, d1.w};

            float ax = 0.0f, ay = 0.0f, az = 0.0f;
            float lim = zm - 3.0e-3f;
            #pragma unroll
            for (int k = 0; k < K_SAMP; k++) {
                if (pf[k] < 0 || zinv[k] <= lim) continue;
                float ew = __expf((zinv[k] - zm) * INV_GAMMA);
                float prob = 1.0f / (1.0f + __expf(dv[k] * INV_SIGMA));
                float w = prob * ew;

                int ff = pf[k];
                uint4    MA = g_packed[ff].a;
                unsigned MB = g_packed[ff].b.x;

                int bk = (pixc * K_SAMP + k) * 3;
                float c0 = bary[bk + 0];
                float c1 = bary[bk + 1];
                float c2 = bary[bk + 2];

                float gx, gy, gz;
                blend_normal(MA, MB, c0, c1, c2, gx, gy, gz);

                ax = fmaf(w, gx, ax);
                ay = fmaf(w, gy, ay);
                az = fmaf(w, gz, az);
            }
            vx = ax + delta;
            vy = ay + delta;
            vz = az + delta;
        }

        float nn  = fmaf(vx, vx, fmaf(vy, vy, vz * vz));
        float inv = rsqrtf(fmaxf(nn, 1e-24f));
        int si = (p * BLK + tid) * 3;
        s[si + 0] = fmaf(vx * inv, 0.5f, 0.5f);
        s[si + 1] = fmaf(vy * inv, 0.5f, 0.5f);
        s[si + 2] = fmaf(vz * inv, 0.5f, 0.5f);
    }

    __syncthreads();

    // ---- coalesced float4 stores ----
    const int NF  = BLK * PPT * 3;       // 1536 floats
    const int NV4 = NF / 4;              // 384
    long fbase  = (long)blockIdx.x * NF;
    long ftotal = (long)npix * 3;
    if (fbase + NF <= ftotal) {
        #pragma unroll
        for (int i = tid; i < NV4; i += BLK) {
            reinterpret_cast<float4*>(out)[fbase / 4 + i] =
                reinterpret_cast<const float4*>(s)[i];
        }
    } else {
        for (int i = tid; i < NF; i += BLK) {
            long fi = fbase + i;
            if (fi < ftotal) out[fi] = s[i];
        }
    }
}

extern "C" void kernel_launch(void* const* d_in, const int* in_sizes, int n_in,
                              void* d_out, int out_size)
{
    const int*   p2f   = (const int*  )d_in[0];
    const float* bary  = (const float*)d_in[1];
    const float* zbuf  = (const float*)d_in[2];
    const float* dists = (const float*)d_in[3];
    const float* vnorm = (const float*)d_in[4];
    const int*   faces = (const int*  )d_in[5];
    float* out = (float*)d_out;

    int F = in_sizes[5] / 3;
    if (F > F_MAX) F = F_MAX;
    int npix = in_sizes[0] / K_SAMP;

    pack_faces_kernel<<<(F + 255) / 256, 256>>>(faces, vnorm, F);

    int blocks = (npix + BLK * PPT - 1) / (BLK * PPT);
    normal_shader_kernel<<<blocks, BLK>>>(p2f, bary, zbuf, dists, out, npix);
}